// round 9
// baseline (speedup 1.0000x reference)
#include <cuda_runtime.h>
#include <cuda_fp16.h>
#include <cuda_bf16.h>

// ---------------- problem constants ----------------
constexpr int NB     = 64;     // batches
constexpr int NODES_ = 116;    // nodes per batch
constexpr int Nn     = NB * NODES_;   // 7424
constexpr int Tt     = 256;
constexpr int Hh     = 32;
constexpr int Ee     = Nn * 128;      // 950272
constexpr int HID    = 64;
constexpr int PPB    = NODES_ / 2;    // node-pairs per batch = 58
constexpr int NGRUB  = NB * PPB;      // 3712 GRU blocks (96 thr each)
constexpr int NTRB   = (Nn / 32) * (Tt / 32);  // 1856 transpose blocks
constexpr int NEDB   = Ee / 256;      // 3712 edge_deg blocks
constexpr int NCSRB  = (Ee + 95) / 96; // 9899 csr blocks (96 thr each, guarded)

typedef unsigned long long ull;

// ---------------- device scratch (no cudaMalloc allowed) ----------------
__device__ __align__(16) float d_xT[(Tt + 1) * Nn]; // transposed x (+1 pad row)
__device__ __align__(16) float d_gruH[Nn * Hh];   // GRU output
__device__ __align__(16) float d_xw[Nn * HID];    // per-layer h @ W^T (fp32, self term)
__device__ __align__(16) __half d_xwh[Nn * HID];  // fp16 copy for gathers
__device__ __align__(16) float d_hbuf[Nn * HID];  // per-layer output
__device__ float d_deg[Nn];
__device__ float d_dis[Nn];
__device__ float d_dis2[Nn];
__device__ __align__(16) int d_cnt[8192];         // padded for int4 scan loads
__device__ int   d_rowptr[Nn + 1];
__device__ int   d_cursor[Nn];
__device__ int   d_order[NB];                     // batches sorted by length desc
__device__ __align__(16) ull d_edge[Ee];          // packed (src:int lo32, coef:f32 hi32)

// ---------------- helpers ----------------
__device__ __forceinline__ float sigm_(float a) {
    return __fdividef(1.0f, 1.0f + __expf(-a));
}
__device__ __forceinline__ float tanh_(float a) {
    return fmaf(-2.0f, __fdividef(1.0f, 1.0f + __expf(2.0f * a)), 1.0f);
}
__device__ __forceinline__ ull fma2_(ull a, ull b, ull c) {
    ull d;
    asm("fma.rn.f32x2 %0, %1, %2, %3;" : "=l"(d) : "l"(a), "l"(b), "l"(c));
    return d;
}
__device__ __forceinline__ ull pack2_(float lo, float hi) {
    ull d;
    asm("mov.b64 %0, {%1, %2};" : "=l"(d) : "f"(lo), "f"(hi));
    return d;
}
__device__ __forceinline__ float hsum2_(ull v) {
    float lo, hi;
    asm("mov.b64 {%0, %1}, %2;" : "=f"(lo), "=f"(hi) : "l"(v));
    return lo + hi;
}

// ---------------- 1) init deg/cnt ----------------
__global__ void init_kernel(float* __restrict__ deg, int* __restrict__ cnt) {
    int i = blockIdx.x * 256 + threadIdx.x;
    if (i < Nn) deg[i] = 1.0f;
    if (i < 8192) cnt[i] = 0;
}

// ---------------- 2) fused: transpose | edge_deg | sort (block-range partition) ----------------
__global__ void __launch_bounds__(256) fused_pre_kernel(
    const float* __restrict__ x, float* __restrict__ xT,
    const int* __restrict__ ei, const float* __restrict__ ea,
    float* __restrict__ deg, int* __restrict__ cnt,
    const int* __restrict__ lengths, int* __restrict__ order) {
    int bid = blockIdx.x;
    int tid = threadIdx.x;
    if (bid < NTRB) {
        // transpose x [N][T] -> [T][N]
        __shared__ float tile[32][33];
        int bx = bid % (Nn / 32), by = bid / (Nn / 32);
        int bn = bx * 32, bt = by * 32;
        int tx = tid & 31, ty = tid >> 5;   // (32, 8)
        #pragma unroll
        for (int j = 0; j < 32; j += 8)
            tile[ty + j][tx] = x[(bn + ty + j) * Tt + (bt + tx)];
        __syncthreads();
        #pragma unroll
        for (int j = 0; j < 32; j += 8)
            xT[(bt + ty + j) * Nn + (bn + tx)] = tile[tx][ty + j];
    } else if (bid < NTRB + NEDB) {
        // degree + in-count histogram
        int e = (bid - NTRB) * 256 + tid;
        int dst = ei[Ee + e];
        atomicAdd(&deg[dst], ea[e]);
        atomicAdd(&cnt[dst], 1);
    } else {
        // rank-sort batches by length (descending)
        __shared__ int sl[NB];
        if (tid < NB) sl[tid] = lengths[tid];
        __syncthreads();
        if (tid < NB) {
            int v = sl[tid];
            int r = 0;
            #pragma unroll
            for (int m = 0; m < NB; m++) {
                int vm = sl[m];
                r += (vm > v) || (vm == v && m < tid);
            }
            order[r] = tid;
        }
    }
}

// ---------------- 3) scan: warp-shuffle two-level -> rowptr/cursor + dis/dis2 ----------------
__global__ void scan_kernel(const int* __restrict__ cnt, const float* __restrict__ deg,
                            int* __restrict__ rowptr, int* __restrict__ cursor,
                            float* __restrict__ dis, float* __restrict__ dis2) {
    __shared__ int swarp[32];
    int tid = threadIdx.x;          // 1024
    int wid = tid >> 5, lane = tid & 31;
    const int4* c4 = (const int4*)cnt;
    int4 v0 = c4[tid * 2];
    int4 v1 = c4[tid * 2 + 1];
    int vals[8] = {v0.x, v0.y, v0.z, v0.w, v1.x, v1.y, v1.z, v1.w};
    int loc[8];
    int s = 0;
    #pragma unroll
    for (int j = 0; j < 8; j++) { loc[j] = s; s += vals[j]; }
    int sc = s;
    #pragma unroll
    for (int off = 1; off < 32; off <<= 1) {
        int n = __shfl_up_sync(0xffffffffu, sc, off);
        if (lane >= off) sc += n;
    }
    if (lane == 31) swarp[wid] = sc;
    __syncthreads();
    if (wid == 0) {
        int w = swarp[lane];
        #pragma unroll
        for (int off = 1; off < 32; off <<= 1) {
            int n = __shfl_up_sync(0xffffffffu, w, off);
            if (lane >= off) w += n;
        }
        swarp[lane] = w;
    }
    __syncthreads();
    int base = (wid > 0 ? swarp[wid - 1] : 0) + (sc - s);  // exclusive prefix
    int idx0 = tid * 8;
    #pragma unroll
    for (int j = 0; j < 8; j++) {
        int idx = idx0 + j;
        if (idx < Nn) {
            int v = base + loc[j];
            rowptr[idx] = v;
            cursor[idx] = v;
        }
    }
    if (tid == 1023) rowptr[Nn] = base + s;
    for (int i = tid; i < Nn; i += 1024) {
        float dg = deg[i];
        float di = rsqrtf(dg);
        dis[i]  = di;
        dis2[i] = di * di;
    }
}

// ---------------- 4) merged: gate-split GRU (bids 0..NGRUB-1) | CSR fill ----------------
// GRU: 96 threads per 2 nodes. Warp g owns gate g (0=R,1=Z,2=N): each thread
// keeps ONE W_hh row (16 packed pairs = 32 regs) -> ~70 regs/thread -> ~2.4x
// occupancy vs the 158-reg all-gates version. Warp N owns h and the update.
__global__ void __launch_bounds__(96) gru_csr_kernel(
    const float* __restrict__ xT, const int* __restrict__ lengths,
    const int* __restrict__ order,
    const float* __restrict__ W_hh, const float* __restrict__ W_ih,
    const float* __restrict__ b_ih, const float* __restrict__ b_hh,
    float* __restrict__ out,
    const int* __restrict__ ei, const float* __restrict__ ea,
    const float* __restrict__ dis, int* __restrict__ cursor,
    ull* __restrict__ edge) {
    int bid = blockIdx.x;
    int tid = threadIdx.x;
    if (bid >= NGRUB) {
        // ---- CSR fill: one edge per thread ----
        int e = (bid - NGRUB) * 96 + tid;
        if (e < Ee) {
            int src = ei[e];
            int dst = ei[Ee + e];
            float c = dis[src] * ea[e] * dis[dst];
            int pos = atomicAdd(&cursor[dst], 1);
            edge[pos] = ((ull)__float_as_uint(c) << 32) | (unsigned)src;
        }
        return;
    }
    // ---- gate-split GRU ----
    __shared__ __align__(16) float sh_h[2][2][32];   // [buf][node][channel]
    __shared__ float sg[2][2][32];                   // [gate r/z][node][channel]
    int wid = tid >> 5;          // 0=R, 1=Z, 2=N
    int j   = tid & 31;          // hidden channel
    int batch = order[bid / PPB];
    int n0 = batch * NODES_ + (bid % PPB) * 2;       // nodes n0, n0+1
    int len = lengths[batch];

    // one gate-row of weights per thread
    int row = wid * 32 + j;
    const float* wrow = &W_hh[row * 32];
    ull wG[16];
    #pragma unroll
    for (int p = 0; p < 16; p++)
        wG[p] = *(const ull*)&wrow[2 * p];
    float wiG = W_ih[row];
    // R/Z: fold both biases into the x-init; N: b_hh goes in the matvec
    // accumulator, b_ih is added with the x-term after the r-scale.
    float b0   = (wid == 2) ? b_hh[64 + j] : (b_ih[row] + b_hh[row]);
    float bNx_ = (wid == 2) ? b_ih[64 + j] : 0.0f;

    float h0 = 0.0f, h1 = 0.0f;   // live only in warp N
    if (wid == 0) {
        sh_h[0][0][j] = 0.0f;
        sh_h[0][1][j] = 0.0f;
    }
    __syncthreads();

    const longlong2* hrd0 = (const longlong2*)sh_h[0][0];
    const longlong2* hrd1 = (const longlong2*)sh_h[0][1];
    float* hwr0 = sh_h[1][0];
    float* hwr1 = sh_h[1][1];

    const float* xp = xT + n0;
    float2 xv = *(const float2*)xp;   // broadcast LDG.64: x for both nodes
    xp += Nn;
    for (int t = 0; t < len; t++) {
        float xt0 = xv.x, xt1 = xv.y;
        xv = *(const float2*)xp;      // row t+1 (pad row Tt on final iter)
        xp += Nn;

        ull a0 = pack2_((wid == 2) ? b0 : fmaf(xt0, wiG, b0), 0.0f);
        ull a1 = pack2_((wid == 2) ? b0 : fmaf(xt1, wiG, b0), 0.0f);
        #pragma unroll
        for (int p = 0; p < 8; p++) {
            longlong2 hv0 = hrd0[p];         // broadcast LDS.128: 4 h of node 0
            longlong2 hv1 = hrd1[p];         // broadcast LDS.128: 4 h of node 1
            a0 = fma2_((ull)hv0.x, wG[2 * p], a0);
            a1 = fma2_((ull)hv1.x, wG[2 * p], a1);
            a0 = fma2_((ull)hv0.y, wG[2 * p + 1], a0);
            a1 = fma2_((ull)hv1.y, wG[2 * p + 1], a1);
        }
        float g0 = hsum2_(a0);
        float g1 = hsum2_(a1);
        if (wid < 2) {                       // R/Z warps publish sigmoid gates
            sg[wid][0][j] = sigm_(g0);
            sg[wid][1][j] = sigm_(g1);
        }
        __syncthreads();
        if (wid == 2) {                      // N warp: candidate + h update
            float r0 = sg[0][0][j], r1 = sg[0][1][j];
            float z0 = sg[1][0][j], z1 = sg[1][1][j];
            float nn0 = tanh_(fmaf(xt0, wiG, bNx_) + r0 * g0);
            float nn1 = tanh_(fmaf(xt1, wiG, bNx_) + r1 * g1);
            h0 = fmaf(z0, h0 - nn0, nn0);    // (1-z)*nn + z*h
            h1 = fmaf(z1, h1 - nn1, nn1);
            hwr0[j] = h0;
            hwr1[j] = h1;
        }
        __syncthreads();
        float* t0 = (float*)hrd0; hrd0 = (const longlong2*)hwr0; hwr0 = t0;
        float* t1 = (float*)hrd1; hrd1 = (const longlong2*)hwr1; hwr1 = t1;
    }
    if (wid == 2) {
        out[n0 * Hh + j]       = h0;
        out[(n0 + 1) * Hh + j] = h1;
    }
}

// ---------------- GEMM: out[n][o] = sum_k in[n][k] * W[o][k]; also fp16 copy ----------------
template <int Kd>
__global__ void gemm_kernel(const float* __restrict__ in, const float* __restrict__ W,
                            float* __restrict__ out, __half* __restrict__ outh) {
    __shared__ float sW[Kd * 64]; // [k][o]
    __shared__ float sh[4 * Kd];
    int tid = threadIdx.x; // 256
    for (int i = tid; i < Kd * 64; i += 256) {
        int k = i >> 6, o = i & 63;
        sW[i] = W[o * Kd + k];
    }
    int nb = blockIdx.x * 4;
    for (int i = tid; i < 4 * Kd; i += 256)
        sh[i] = in[nb * Kd + i];
    __syncthreads();
    int ln = tid >> 6, o = tid & 63;
    float acc = 0.0f;
    #pragma unroll
    for (int k = 0; k < Kd; k++)
        acc = fmaf(sh[ln * Kd + k], sW[k * 64 + o], acc);
    out[(nb + ln) * 64 + o]  = acc;
    outh[(nb + ln) * 64 + o] = __float2half(acc);
}

// ---------------- aggregation: fp16 gather over dst-CSR + fp32 self + bias + PReLU ----------------
__global__ void agg_kernel(const float* __restrict__ xw, const __half* __restrict__ xwh,
                           const float* __restrict__ dis2,
                           const int* __restrict__ rowptr, const ull* __restrict__ edge,
                           const float* __restrict__ bias,
                           const float* __restrict__ prelu_a, int layer,
                           float* __restrict__ out) {
    int tid = threadIdx.x;           // 128 -> 8 nodes per block, 16 lanes per node
    int n = blockIdx.x * 8 + (tid >> 4);
    int l = tid & 15;
    int lane = tid & 31;
    unsigned gmask = 0xFFFFu << (lane & 16);

    const float4* __restrict__ xw4 = (const float4*)xw;
    const uint2* __restrict__ xh = (const uint2*)xwh;   // 4 halves per element
    float4 acc = xw4[n * 16 + l];
    float d2 = dis2[n];
    acc.x *= d2; acc.y *= d2; acc.z *= d2; acc.w *= d2;

    int e0 = rowptr[n], e1 = rowptr[n + 1];
    for (int e = e0; e < e1; e += 16) {
        ull rec = 0;                              // zero coef pads partial chunks
        if (e + l < e1) rec = edge[e + l];
        #pragma unroll
        for (int m = 0; m < 16; m++) {
            ull rm = __shfl_sync(gmask, rec, m, 16);
            int   sm = (int)(unsigned)rm;
            float cm = __uint_as_float((unsigned)(rm >> 32));
            uint2 hv = xh[sm * 16 + l];
            float2 f0 = __half22float2(*(__half2*)&hv.x);
            float2 f1 = __half22float2(*(__half2*)&hv.y);
            acc.x = fmaf(cm, f0.x, acc.x); acc.y = fmaf(cm, f0.y, acc.y);
            acc.z = fmaf(cm, f1.x, acc.z); acc.w = fmaf(cm, f1.y, acc.w);
        }
    }
    float4 b4 = ((const float4*)bias)[l];
    acc.x += b4.x; acc.y += b4.y; acc.z += b4.z; acc.w += b4.w;
    float a = prelu_a[layer];
    acc.x = (acc.x >= 0.f) ? acc.x : a * acc.x;
    acc.y = (acc.y >= 0.f) ? acc.y : a * acc.y;
    acc.z = (acc.z >= 0.f) ? acc.z : a * acc.z;
    acc.w = (acc.w >= 0.f) ? acc.w : a * acc.w;
    ((float4*)out)[n * 16 + l] = acc;
}

// ---------------- graph mean pooling ----------------
__global__ void graph_kernel(const float* __restrict__ node_emb, float* __restrict__ gout) {
    int b = blockIdx.x;   // 64
    int d = threadIdx.x;  // 64
    float s = 0.0f;
    #pragma unroll 8
    for (int i = 0; i < NODES_; i++)
        s += node_emb[(b * NODES_ + i) * 64 + d];
    gout[b * 64 + d] = s * (1.0f / (float)NODES_);
}

// ---------------- launch (single stream; overlap via fused grid partitions) ----------------
extern "C" void kernel_launch(void* const* d_in, const int* in_sizes, int n_in,
                              void* d_out, int out_size) {
    const float* x       = (const float*)d_in[0];
    const int*   ei      = (const int*)d_in[1];
    const float* ea      = (const float*)d_in[2];
    const int*   lengths = (const int*)d_in[3];
    // d_in[4] = batch (unused; batch[n] == n / NODES_)
    const float* W_ih    = (const float*)d_in[5];
    const float* W_hh    = (const float*)d_in[6];
    const float* b_ih    = (const float*)d_in[7];
    const float* b_hh    = (const float*)d_in[8];
    const float* g_w0    = (const float*)d_in[9];
    const float* g_b0    = (const float*)d_in[10];
    const float* g_ws    = (const float*)d_in[11];
    const float* g_bs    = (const float*)d_in[12];
    const float* prelu_a = (const float*)d_in[13];
    float* out = (float*)d_out;

    float *xT, *gruH, *xw, *hbuf, *deg, *dis, *dis2;
    __half* xwh;
    int *cnt, *rowptr, *cursor, *order;
    ull* edge;
    cudaGetSymbolAddress((void**)&xT,     d_xT);
    cudaGetSymbolAddress((void**)&gruH,   d_gruH);
    cudaGetSymbolAddress((void**)&xw,     d_xw);
    cudaGetSymbolAddress((void**)&xwh,    d_xwh);
    cudaGetSymbolAddress((void**)&hbuf,   d_hbuf);
    cudaGetSymbolAddress((void**)&deg,    d_deg);
    cudaGetSymbolAddress((void**)&dis,    d_dis);
    cudaGetSymbolAddress((void**)&dis2,   d_dis2);
    cudaGetSymbolAddress((void**)&cnt,    d_cnt);
    cudaGetSymbolAddress((void**)&rowptr, d_rowptr);
    cudaGetSymbolAddress((void**)&cursor, d_cursor);
    cudaGetSymbolAddress((void**)&order,  d_order);
    cudaGetSymbolAddress((void**)&edge,   d_edge);

    // 1: init deg/cnt
    init_kernel<<<8192 / 256, 256>>>(deg, cnt);
    // 2: fused transpose | edge_deg | sort
    fused_pre_kernel<<<NTRB + NEDB + 1, 256>>>(x, xT, ei, ea, deg, cnt, lengths, order);
    // 3: scan -> rowptr/cursor/dis
    scan_kernel<<<1, 1024>>>(cnt, deg, rowptr, cursor, dis, dis2);
    // 4: merged gate-split GRU | CSR fill  (profiled slot)
    gru_csr_kernel<<<NGRUB + NCSRB, 96>>>(xT, lengths, order, W_hh, W_ih, b_ih, b_hh,
                                          gruH, ei, ea, dis, cursor, edge);

    // GCN layers
    gemm_kernel<32><<<Nn / 4, 256>>>(gruH, g_w0, xw, xwh);
    agg_kernel<<<Nn / 8, 128>>>(xw, xwh, dis2, rowptr, edge, g_b0, prelu_a, 0, hbuf);
    for (int i = 1; i < 4; i++) {
        gemm_kernel<64><<<Nn / 4, 256>>>(hbuf, g_ws + (i - 1) * 64 * 64, xw, xwh);
        float* dst = (i == 3) ? out : hbuf;
        agg_kernel<<<Nn / 8, 128>>>(xw, xwh, dis2, rowptr, edge,
                                    g_bs + (i - 1) * 64, prelu_a, i, dst);
    }

    // graph embedding appended after node embeddings
    graph_kernel<<<NB, 64>>>(out, out + Nn * 64);
}

// round 10
// speedup vs baseline: 1.1001x; 1.1001x over previous
#include <cuda_runtime.h>
#include <cuda_fp16.h>
#include <cuda_bf16.h>

// ---------------- problem constants ----------------
constexpr int NB     = 64;     // batches
constexpr int NODES_ = 116;    // nodes per batch
constexpr int Nn     = NB * NODES_;   // 7424
constexpr int Tt     = 256;
constexpr int Hh     = 32;
constexpr int Ee     = Nn * 128;      // 950272
constexpr int HID    = 64;
constexpr int BPB2   = NODES_ / 4;    // GRU blocks per batch = 29 (4 nodes/block)
constexpr int NGRUB  = NB * BPB2;     // 1856 GRU blocks
constexpr int NTRB   = (Nn / 32) * (Tt / 32);  // 1856 transpose blocks
constexpr int NEDB   = Ee / 256;      // 3712 edge_deg blocks
constexpr int NCSRB  = Ee / 64;       // 14848 csr blocks (64 thr each)

typedef unsigned long long ull;

// ---------------- device scratch (no cudaMalloc allowed) ----------------
__device__ __align__(16) float d_xT[(Tt + 1) * Nn]; // transposed x (+1 pad row)
__device__ __align__(16) float d_gruH[Nn * Hh];   // GRU output
__device__ __align__(16) float d_xw[Nn * HID];    // per-layer h @ W^T (fp32, self term)
__device__ __align__(16) __half d_xwh[Nn * HID];  // fp16 copy for gathers
__device__ __align__(16) float d_hbuf[Nn * HID];  // per-layer output
__device__ float d_deg[Nn];
__device__ float d_dis[Nn];
__device__ float d_dis2[Nn];
__device__ __align__(16) int d_cnt[8192];         // padded for int4 scan loads
__device__ int   d_rowptr[Nn + 1];
__device__ int   d_cursor[Nn];
__device__ int   d_order[NB];                     // batches sorted by length desc
__device__ __align__(16) ull d_edge[Ee];          // packed (src:int lo32, coef:f32 hi32)

// ---------------- helpers ----------------
__device__ __forceinline__ float sigm_(float a) {
    return __fdividef(1.0f, 1.0f + __expf(-a));
}
__device__ __forceinline__ float tanh_(float a) {
    return fmaf(-2.0f, __fdividef(1.0f, 1.0f + __expf(2.0f * a)), 1.0f);
}
__device__ __forceinline__ ull fma2_(ull a, ull b, ull c) {
    ull d;
    asm("fma.rn.f32x2 %0, %1, %2, %3;" : "=l"(d) : "l"(a), "l"(b), "l"(c));
    return d;
}
__device__ __forceinline__ ull pack2_(float lo, float hi) {
    ull d;
    asm("mov.b64 %0, {%1, %2};" : "=l"(d) : "f"(lo), "f"(hi));
    return d;
}
__device__ __forceinline__ float hsum2_(ull v) {
    float lo, hi;
    asm("mov.b64 {%0, %1}, %2;" : "=f"(lo), "=f"(hi) : "l"(v));
    return lo + hi;
}

// ---------------- 1) init deg/cnt ----------------
__global__ void init_kernel(float* __restrict__ deg, int* __restrict__ cnt) {
    int i = blockIdx.x * 256 + threadIdx.x;
    if (i < Nn) deg[i] = 1.0f;
    if (i < 8192) cnt[i] = 0;
}

// ---------------- 2) fused: transpose | edge_deg | sort (block-range partition) ----------------
__global__ void __launch_bounds__(256) fused_pre_kernel(
    const float* __restrict__ x, float* __restrict__ xT,
    const int* __restrict__ ei, const float* __restrict__ ea,
    float* __restrict__ deg, int* __restrict__ cnt,
    const int* __restrict__ lengths, int* __restrict__ order) {
    int bid = blockIdx.x;
    int tid = threadIdx.x;
    if (bid < NTRB) {
        // transpose x [N][T] -> [T][N]
        __shared__ float tile[32][33];
        int bx = bid % (Nn / 32), by = bid / (Nn / 32);
        int bn = bx * 32, bt = by * 32;
        int tx = tid & 31, ty = tid >> 5;   // (32, 8)
        #pragma unroll
        for (int j = 0; j < 32; j += 8)
            tile[ty + j][tx] = x[(bn + ty + j) * Tt + (bt + tx)];
        __syncthreads();
        #pragma unroll
        for (int j = 0; j < 32; j += 8)
            xT[(bt + ty + j) * Nn + (bn + tx)] = tile[tx][ty + j];
    } else if (bid < NTRB + NEDB) {
        // degree + in-count histogram
        int e = (bid - NTRB) * 256 + tid;
        int dst = ei[Ee + e];
        atomicAdd(&deg[dst], ea[e]);
        atomicAdd(&cnt[dst], 1);
    } else {
        // rank-sort batches by length (descending)
        __shared__ int sl[NB];
        if (tid < NB) sl[tid] = lengths[tid];
        __syncthreads();
        if (tid < NB) {
            int v = sl[tid];
            int r = 0;
            #pragma unroll
            for (int m = 0; m < NB; m++) {
                int vm = sl[m];
                r += (vm > v) || (vm == v && m < tid);
            }
            order[r] = tid;
        }
    }
}

// ---------------- 3) scan: warp-shuffle two-level -> rowptr/cursor + dis/dis2 ----------------
__global__ void scan_kernel(const int* __restrict__ cnt, const float* __restrict__ deg,
                            int* __restrict__ rowptr, int* __restrict__ cursor,
                            float* __restrict__ dis, float* __restrict__ dis2) {
    __shared__ int swarp[32];
    int tid = threadIdx.x;          // 1024
    int wid = tid >> 5, lane = tid & 31;
    const int4* c4 = (const int4*)cnt;
    int4 v0 = c4[tid * 2];
    int4 v1 = c4[tid * 2 + 1];
    int vals[8] = {v0.x, v0.y, v0.z, v0.w, v1.x, v1.y, v1.z, v1.w};
    int loc[8];
    int s = 0;
    #pragma unroll
    for (int j = 0; j < 8; j++) { loc[j] = s; s += vals[j]; }
    int sc = s;
    #pragma unroll
    for (int off = 1; off < 32; off <<= 1) {
        int n = __shfl_up_sync(0xffffffffu, sc, off);
        if (lane >= off) sc += n;
    }
    if (lane == 31) swarp[wid] = sc;
    __syncthreads();
    if (wid == 0) {
        int w = swarp[lane];
        #pragma unroll
        for (int off = 1; off < 32; off <<= 1) {
            int n = __shfl_up_sync(0xffffffffu, w, off);
            if (lane >= off) w += n;
        }
        swarp[lane] = w;
    }
    __syncthreads();
    int base = (wid > 0 ? swarp[wid - 1] : 0) + (sc - s);  // exclusive prefix
    int idx0 = tid * 8;
    #pragma unroll
    for (int j = 0; j < 8; j++) {
        int idx = idx0 + j;
        if (idx < Nn) {
            int v = base + loc[j];
            rowptr[idx] = v;
            cursor[idx] = v;
        }
    }
    if (tid == 1023) rowptr[Nn] = base + s;
    for (int i = tid; i < Nn; i += 1024) {
        float dg = deg[i];
        float di = rsqrtf(dg);
        dis[i]  = di;
        dis2[i] = di * di;
    }
}

// ---------------- 4) merged: GRU (bids 0..NGRUB-1) | CSR fill (rest)  ----------------
// GRU: 2 nodes per warp, register-resident packed weights, double-buffered h row.
// (verified round-8 version: best measured config, fma 50.1%, 218.7us merged)
__global__ void __launch_bounds__(64) gru_csr_kernel(
    const float* __restrict__ xT, const int* __restrict__ lengths,
    const int* __restrict__ order,
    const float* __restrict__ W_hh, const float* __restrict__ W_ih,
    const float* __restrict__ b_ih, const float* __restrict__ b_hh,
    float* __restrict__ out,
    const int* __restrict__ ei, const float* __restrict__ ea,
    const float* __restrict__ dis, int* __restrict__ cursor,
    ull* __restrict__ edge) {
    int bid = blockIdx.x;
    int tid = threadIdx.x;
    if (bid >= NGRUB) {
        // ---- CSR fill: one edge per thread ----
        int e = (bid - NGRUB) * 64 + tid;
        int src = ei[e];
        int dst = ei[Ee + e];
        float c = dis[src] * ea[e] * dis[dst];
        int pos = atomicAdd(&cursor[dst], 1);
        edge[pos] = ((ull)__float_as_uint(c) << 32) | (unsigned)src;
        return;
    }
    // ---- GRU ----
    __shared__ __align__(16) float sh_h[2][4][32];   // [buf][node-in-block][channel]
    int wid = tid >> 5;          // warp id (2 warps/block)
    int j   = tid & 31;          // hidden channel
    int batch = order[bid / BPB2];
    int n0 = batch * NODES_ + (bid % BPB2) * 4 + wid * 2;  // nodes n0, n0+1
    int len = lengths[batch];    // uniform across warp

    ull wR[16], wZ[16], wN[16];
    #pragma unroll
    for (int p = 0; p < 16; p++) {
        wR[p] = *(const ull*)&W_hh[(j     ) * 32 + 2 * p];
        wZ[p] = *(const ull*)&W_hh[(32 + j) * 32 + 2 * p];
        wN[p] = *(const ull*)&W_hh[(64 + j) * 32 + 2 * p];
    }
    float wiR = W_ih[j], wiZ = W_ih[32 + j], wiN = W_ih[64 + j];
    float bR  = b_ih[j]      + b_hh[j];
    float bZ  = b_ih[32 + j] + b_hh[32 + j];
    float bNx = b_ih[64 + j];
    float bNh = b_hh[64 + j];

    int ra = wid * 2, rb = wid * 2 + 1;
    float h0 = 0.0f, h1 = 0.0f;
    sh_h[0][ra][j] = 0.0f;
    sh_h[0][rb][j] = 0.0f;
    __syncwarp();

    const longlong2* hrdA = (const longlong2*)sh_h[0][ra];
    const longlong2* hrdB = (const longlong2*)sh_h[0][rb];
    float* hwrA = sh_h[1][ra];
    float* hwrB = sh_h[1][rb];

    const float* xp = xT + n0;
    float2 xv = *(const float2*)xp;   // broadcast LDG.64: x for both nodes
    xp += Nn;
    for (int t = 0; t < len; t++) {
        float xt0 = xv.x, xt1 = xv.y;
        xv = *(const float2*)xp;      // row t+1 (pad row Tt on final iter)
        xp += Nn;

        ull aR0 = pack2_(fmaf(xt0, wiR, bR), 0.0f);
        ull aZ0 = pack2_(fmaf(xt0, wiZ, bZ), 0.0f);
        ull aN0 = pack2_(bNh, 0.0f);
        ull aR1 = pack2_(fmaf(xt1, wiR, bR), 0.0f);
        ull aZ1 = pack2_(fmaf(xt1, wiZ, bZ), 0.0f);
        ull aN1 = pack2_(bNh, 0.0f);
        #pragma unroll
        for (int p = 0; p < 8; p++) {
            longlong2 ha = hrdA[p];          // broadcast LDS.128: 4 h of node 0
            longlong2 hb = hrdB[p];          // broadcast LDS.128: 4 h of node 1
            ull a0 = (ull)ha.x, a1 = (ull)ha.y;
            ull b0 = (ull)hb.x, b1 = (ull)hb.y;
            aR0 = fma2_(a0, wR[2 * p], aR0);
            aR1 = fma2_(b0, wR[2 * p], aR1);
            aZ0 = fma2_(a0, wZ[2 * p], aZ0);
            aZ1 = fma2_(b0, wZ[2 * p], aZ1);
            aN0 = fma2_(a0, wN[2 * p], aN0);
            aN1 = fma2_(b0, wN[2 * p], aN1);
            aR0 = fma2_(a1, wR[2 * p + 1], aR0);
            aR1 = fma2_(b1, wR[2 * p + 1], aR1);
            aZ0 = fma2_(a1, wZ[2 * p + 1], aZ0);
            aZ1 = fma2_(b1, wZ[2 * p + 1], aZ1);
            aN0 = fma2_(a1, wN[2 * p + 1], aN0);
            aN1 = fma2_(b1, wN[2 * p + 1], aN1);
        }
        float r0 = sigm_(hsum2_(aR0));
        float r1 = sigm_(hsum2_(aR1));
        float z0 = sigm_(hsum2_(aZ0));
        float z1 = sigm_(hsum2_(aZ1));
        float nn0 = tanh_(fmaf(xt0, wiN, bNx) + r0 * hsum2_(aN0));
        float nn1 = tanh_(fmaf(xt1, wiN, bNx) + r1 * hsum2_(aN1));
        h0 = fmaf(z0, h0 - nn0, nn0);        // (1-z)*nn + z*h
        h1 = fmaf(z1, h1 - nn1, nn1);
        hwrA[j] = h0;
        hwrB[j] = h1;
        __syncwarp();
        float* tA = (float*)hrdA; hrdA = (const longlong2*)hwrA; hwrA = tA;
        float* tB = (float*)hrdB; hrdB = (const longlong2*)hwrB; hwrB = tB;
    }
    out[n0 * Hh + j]       = h0;
    out[(n0 + 1) * Hh + j] = h1;
}

// ---------------- GEMM: out[n][o] = sum_k in[n][k] * W[o][k]; also fp16 copy ----------------
template <int Kd>
__global__ void gemm_kernel(const float* __restrict__ in, const float* __restrict__ W,
                            float* __restrict__ out, __half* __restrict__ outh) {
    __shared__ float sW[Kd * 64]; // [k][o]
    __shared__ float sh[4 * Kd];
    int tid = threadIdx.x; // 256
    for (int i = tid; i < Kd * 64; i += 256) {
        int k = i >> 6, o = i & 63;
        sW[i] = W[o * Kd + k];
    }
    int nb = blockIdx.x * 4;
    for (int i = tid; i < 4 * Kd; i += 256)
        sh[i] = in[nb * Kd + i];
    __syncthreads();
    int ln = tid >> 6, o = tid & 63;
    float acc = 0.0f;
    #pragma unroll
    for (int k = 0; k < Kd; k++)
        acc = fmaf(sh[ln * Kd + k], sW[k * 64 + o], acc);
    out[(nb + ln) * 64 + o]  = acc;
    outh[(nb + ln) * 64 + o] = __float2half(acc);
}

// ---------------- aggregation: fp16 gather over dst-CSR + fp32 self + bias + PReLU ----------------
// Edge records double-buffered: next chunk's LDG.64 issues before the current
// chunk's 16 gathers consume it, hiding the ~234cyc L2 latency per chunk.
__global__ void agg_kernel(const float* __restrict__ xw, const __half* __restrict__ xwh,
                           const float* __restrict__ dis2,
                           const int* __restrict__ rowptr, const ull* __restrict__ edge,
                           const float* __restrict__ bias,
                           const float* __restrict__ prelu_a, int layer,
                           float* __restrict__ out) {
    int tid = threadIdx.x;           // 128 -> 8 nodes per block, 16 lanes per node
    int n = blockIdx.x * 8 + (tid >> 4);
    int l = tid & 15;
    int lane = tid & 31;
    unsigned gmask = 0xFFFFu << (lane & 16);

    const float4* __restrict__ xw4 = (const float4*)xw;
    const uint2* __restrict__ xh = (const uint2*)xwh;   // 4 halves per element
    float4 acc = xw4[n * 16 + l];
    float d2 = dis2[n];
    acc.x *= d2; acc.y *= d2; acc.z *= d2; acc.w *= d2;

    int e0 = rowptr[n], e1 = rowptr[n + 1];
    ull rec = 0;
    if (e0 + l < e1) rec = edge[e0 + l];              // first chunk
    for (int e = e0; e < e1; e += 16) {
        ull cur = rec;
        rec = 0;
        if (e + 16 + l < e1) rec = edge[e + 16 + l];  // prefetch next chunk
        #pragma unroll
        for (int m = 0; m < 16; m++) {
            ull rm = __shfl_sync(gmask, cur, m, 16);
            int   sm = (int)(unsigned)rm;
            float cm = __uint_as_float((unsigned)(rm >> 32));
            uint2 hv = xh[sm * 16 + l];
            float2 f0 = __half22float2(*(__half2*)&hv.x);
            float2 f1 = __half22float2(*(__half2*)&hv.y);
            acc.x = fmaf(cm, f0.x, acc.x); acc.y = fmaf(cm, f0.y, acc.y);
            acc.z = fmaf(cm, f1.x, acc.z); acc.w = fmaf(cm, f1.y, acc.w);
        }
    }
    float4 b4 = ((const float4*)bias)[l];
    acc.x += b4.x; acc.y += b4.y; acc.z += b4.z; acc.w += b4.w;
    float a = prelu_a[layer];
    acc.x = (acc.x >= 0.f) ? acc.x : a * acc.x;
    acc.y = (acc.y >= 0.f) ? acc.y : a * acc.y;
    acc.z = (acc.z >= 0.f) ? acc.z : a * acc.z;
    acc.w = (acc.w >= 0.f) ? acc.w : a * acc.w;
    ((float4*)out)[n * 16 + l] = acc;
}

// ---------------- graph mean pooling ----------------
__global__ void graph_kernel(const float* __restrict__ node_emb, float* __restrict__ gout) {
    int b = blockIdx.x;   // 64
    int d = threadIdx.x;  // 64
    float s = 0.0f;
    #pragma unroll 8
    for (int i = 0; i < NODES_; i++)
        s += node_emb[(b * NODES_ + i) * 64 + d];
    gout[b * 64 + d] = s * (1.0f / (float)NODES_);
}

// ---------------- launch (single stream; overlap via fused grid partitions) ----------------
extern "C" void kernel_launch(void* const* d_in, const int* in_sizes, int n_in,
                              void* d_out, int out_size) {
    const float* x       = (const float*)d_in[0];
    const int*   ei      = (const int*)d_in[1];
    const float* ea      = (const float*)d_in[2];
    const int*   lengths = (const int*)d_in[3];
    // d_in[4] = batch (unused; batch[n] == n / NODES_)
    const float* W_ih    = (const float*)d_in[5];
    const float* W_hh    = (const float*)d_in[6];
    const float* b_ih    = (const float*)d_in[7];
    const float* b_hh    = (const float*)d_in[8];
    const float* g_w0    = (const float*)d_in[9];
    const float* g_b0    = (const float*)d_in[10];
    const float* g_ws    = (const float*)d_in[11];
    const float* g_bs    = (const float*)d_in[12];
    const float* prelu_a = (const float*)d_in[13];
    float* out = (float*)d_out;

    float *xT, *gruH, *xw, *hbuf, *deg, *dis, *dis2;
    __half* xwh;
    int *cnt, *rowptr, *cursor, *order;
    ull* edge;
    cudaGetSymbolAddress((void**)&xT,     d_xT);
    cudaGetSymbolAddress((void**)&gruH,   d_gruH);
    cudaGetSymbolAddress((void**)&xw,     d_xw);
    cudaGetSymbolAddress((void**)&xwh,    d_xwh);
    cudaGetSymbolAddress((void**)&hbuf,   d_hbuf);
    cudaGetSymbolAddress((void**)&deg,    d_deg);
    cudaGetSymbolAddress((void**)&dis,    d_dis);
    cudaGetSymbolAddress((void**)&dis2,   d_dis2);
    cudaGetSymbolAddress((void**)&cnt,    d_cnt);
    cudaGetSymbolAddress((void**)&rowptr, d_rowptr);
    cudaGetSymbolAddress((void**)&cursor, d_cursor);
    cudaGetSymbolAddress((void**)&order,  d_order);
    cudaGetSymbolAddress((void**)&edge,   d_edge);

    // 1: init deg/cnt
    init_kernel<<<8192 / 256, 256>>>(deg, cnt);
    // 2: fused transpose | edge_deg | sort
    fused_pre_kernel<<<NTRB + NEDB + 1, 256>>>(x, xT, ei, ea, deg, cnt, lengths, order);
    // 3: scan -> rowptr/cursor/dis
    scan_kernel<<<1, 1024>>>(cnt, deg, rowptr, cursor, dis, dis2);
    // 4: merged GRU | CSR fill
    gru_csr_kernel<<<NGRUB + NCSRB, 64>>>(xT, lengths, order, W_hh, W_ih, b_ih, b_hh,
                                          gruH, ei, ea, dis, cursor, edge);

    // GCN layers
    gemm_kernel<32><<<Nn / 4, 256>>>(gruH, g_w0, xw, xwh);
    agg_kernel<<<Nn / 8, 128>>>(xw, xwh, dis2, rowptr, edge, g_b0, prelu_a, 0, hbuf);
    for (int i = 1; i < 4; i++) {
        gemm_kernel<64><<<Nn / 4, 256>>>(hbuf, g_ws + (i - 1) * 64 * 64, xw, xwh);
        float* dst = (i == 3) ? out : hbuf;
        agg_kernel<<<Nn / 8, 128>>>(xw, xwh, dis2, rowptr, edge,
                                    g_bs + (i - 1) * 64, prelu_a, i, dst);
    }

    // graph embedding appended after node embeddings
    graph_kernel<<<NB, 64>>>(out, out + Nn * 64);
}

// round 11
// speedup vs baseline: 1.4713x; 1.3374x over previous
#include <cuda_runtime.h>
#include <cuda_fp16.h>
#include <cuda_bf16.h>

// ---------------- problem constants ----------------
constexpr int NB     = 64;     // batches
constexpr int NODES_ = 116;    // nodes per batch
constexpr int Nn     = NB * NODES_;   // 7424
constexpr int Tt     = 256;
constexpr int Hh     = 32;
constexpr int Ee     = Nn * 128;      // 950272
constexpr int HID    = 64;
constexpr int BPB2   = NODES_ / 4;    // GRU blocks per batch = 29 (4 nodes/block)
constexpr int NGRUB  = NB * BPB2;     // 1856 GRU blocks
constexpr int NTRB   = (Nn / 32) * (Tt / 32);  // 1856 transpose blocks
constexpr int NEDB   = Ee / 256;      // 3712 edge_deg blocks
constexpr int NCSRB  = Ee / 64;       // 14848 csr blocks (64 thr each)
constexpr int NPREB  = NTRB + NEDB + 1;  // fused_pre grid

typedef unsigned long long ull;

// ---------------- device scratch (no cudaMalloc allowed) ----------------
__device__ __align__(16) float d_xT[(Tt + 1) * Nn]; // transposed x (+1 pad row)
__device__ __align__(16) float d_xwA[Nn * HID];   // layer input fp32 (ping)
__device__ __align__(16) __half d_xwhA[Nn * HID]; // layer input fp16 (ping)
__device__ __align__(16) float d_xwB[Nn * HID];   // layer input fp32 (pong)
__device__ __align__(16) __half d_xwhB[Nn * HID]; // layer input fp16 (pong)
__device__ float d_deg[Nn];
__device__ float d_dis[Nn];
__device__ float d_dis2[Nn];
__device__ __align__(16) int d_cnt[8192];         // padded for int4 scan loads
__device__ int   d_rowptr[Nn + 1];
__device__ int   d_cursor[Nn];
__device__ int   d_order[NB];                     // batches sorted by length desc
__device__ unsigned d_done;                       // fused_pre completion counter
__device__ __align__(16) ull d_edge[Ee];          // packed (src:int lo32, coef:f32 hi32)

// ---------------- helpers ----------------
__device__ __forceinline__ float sigm_(float a) {
    return __fdividef(1.0f, 1.0f + __expf(-a));
}
__device__ __forceinline__ float tanh_(float a) {
    return fmaf(-2.0f, __fdividef(1.0f, 1.0f + __expf(2.0f * a)), 1.0f);
}
__device__ __forceinline__ ull fma2_(ull a, ull b, ull c) {
    ull d;
    asm("fma.rn.f32x2 %0, %1, %2, %3;" : "=l"(d) : "l"(a), "l"(b), "l"(c));
    return d;
}
__device__ __forceinline__ ull pack2_(float lo, float hi) {
    ull d;
    asm("mov.b64 %0, {%1, %2};" : "=l"(d) : "f"(lo), "f"(hi));
    return d;
}
__device__ __forceinline__ float hsum2_(ull v) {
    float lo, hi;
    asm("mov.b64 {%0, %1}, %2;" : "=f"(lo), "=f"(hi) : "l"(v));
    return lo + hi;
}

// ---------------- 1) init deg/cnt/done ----------------
__global__ void init_kernel(float* __restrict__ deg, int* __restrict__ cnt) {
    int i = blockIdx.x * 256 + threadIdx.x;
    if (i == 0) d_done = 0;
    if (i < Nn) deg[i] = 1.0f;
    if (i < 8192) cnt[i] = 0;
}

// ---------------- 2) fused: transpose | edge_deg | sort, + last-block scan ----------------
__global__ void __launch_bounds__(256) fused_pre_kernel(
    const float* __restrict__ x, float* __restrict__ xT,
    const int* __restrict__ ei, const float* __restrict__ ea,
    float* __restrict__ deg, int* __restrict__ cnt,
    const int* __restrict__ lengths, int* __restrict__ order,
    int* __restrict__ rowptr, int* __restrict__ cursor,
    float* __restrict__ dis, float* __restrict__ dis2) {
    int bid = blockIdx.x;
    int tid = threadIdx.x;
    if (bid < NTRB) {
        // transpose x [N][T] -> [T][N]
        __shared__ float tile[32][33];
        int bx = bid % (Nn / 32), by = bid / (Nn / 32);
        int bn = bx * 32, bt = by * 32;
        int tx = tid & 31, ty = tid >> 5;   // (32, 8)
        #pragma unroll
        for (int j = 0; j < 32; j += 8)
            tile[ty + j][tx] = x[(bn + ty + j) * Tt + (bt + tx)];
        __syncthreads();
        #pragma unroll
        for (int j = 0; j < 32; j += 8)
            xT[(bt + ty + j) * Nn + (bn + tx)] = tile[tx][ty + j];
    } else if (bid < NTRB + NEDB) {
        // degree + in-count histogram
        int e = (bid - NTRB) * 256 + tid;
        int dst = ei[Ee + e];
        atomicAdd(&deg[dst], ea[e]);
        atomicAdd(&cnt[dst], 1);
    } else {
        // rank-sort batches by length (descending)
        __shared__ int sl[NB];
        if (tid < NB) sl[tid] = lengths[tid];
        __syncthreads();
        if (tid < NB) {
            int v = sl[tid];
            int r = 0;
            #pragma unroll
            for (int m = 0; m < NB; m++) {
                int vm = sl[m];
                r += (vm > v) || (vm == v && m < tid);
            }
            order[r] = tid;
        }
    }

    // ---- last-block scan: rowptr/cursor + dis/dis2 ----
    __threadfence();
    __syncthreads();
    __shared__ unsigned rank_s;
    if (tid == 0) rank_s = atomicAdd(&d_done, 1u);
    __syncthreads();
    if (rank_s != NPREB - 1) return;
    __threadfence();    // acquire: all other blocks' writes now visible

    __shared__ int swarp[8];
    int wid = tid >> 5, lane = tid & 31;
    const int4* c4 = (const int4*)cnt;
    int pref[32];
    int s = 0;
    #pragma unroll
    for (int q = 0; q < 8; q++) {
        int4 v = c4[tid * 8 + q];
        pref[4 * q]     = s; s += v.x;
        pref[4 * q + 1] = s; s += v.y;
        pref[4 * q + 2] = s; s += v.z;
        pref[4 * q + 3] = s; s += v.w;
    }
    int sc = s;
    #pragma unroll
    for (int off = 1; off < 32; off <<= 1) {
        int n = __shfl_up_sync(0xffffffffu, sc, off);
        if (lane >= off) sc += n;
    }
    if (lane == 31) swarp[wid] = sc;
    __syncthreads();
    if (tid == 0) {
        int r = 0;
        #pragma unroll
        for (int w = 0; w < 8; w++) { r += swarp[w]; swarp[w] = r; }
    }
    __syncthreads();
    int base = (wid > 0 ? swarp[wid - 1] : 0) + (sc - s);  // exclusive prefix
    int idx0 = tid * 32;
    #pragma unroll
    for (int j = 0; j < 32; j++) {
        int idx = idx0 + j;
        if (idx < Nn) {
            int v = base + pref[j];
            rowptr[idx] = v;
            cursor[idx] = v;
        }
    }
    if (tid == 255) rowptr[Nn] = swarp[7];
    for (int i = tid; i < Nn; i += 256) {
        float dg = deg[i];
        float di = rsqrtf(dg);
        dis[i]  = di;
        dis2[i] = di * di;
    }
}

// ---------------- 3) merged: GRU+gemm0 (bids 0..NGRUB-1) | CSR fill (rest) ----------------
// GRU: 2 nodes per warp, register-resident packed weights (verified round-8 core).
// Epilogue: block computes xw0 = h @ W0^T for its own 4 nodes (no grid dep).
__global__ void __launch_bounds__(64) gru_csr_kernel(
    const float* __restrict__ xT, const int* __restrict__ lengths,
    const int* __restrict__ order,
    const float* __restrict__ W_hh, const float* __restrict__ W_ih,
    const float* __restrict__ b_ih, const float* __restrict__ b_hh,
    const float* __restrict__ W0,
    float* __restrict__ xw_out, __half* __restrict__ xwh_out,
    const int* __restrict__ ei, const float* __restrict__ ea,
    const float* __restrict__ dis, int* __restrict__ cursor,
    ull* __restrict__ edge) {
    int bid = blockIdx.x;
    int tid = threadIdx.x;
    if (bid >= NGRUB) {
        // ---- CSR fill: one edge per thread ----
        int e = (bid - NGRUB) * 64 + tid;
        int src = ei[e];
        int dst = ei[Ee + e];
        float c = dis[src] * ea[e] * dis[dst];
        int pos = atomicAdd(&cursor[dst], 1);
        edge[pos] = ((ull)__float_as_uint(c) << 32) | (unsigned)src;
        return;
    }
    // ---- GRU ----
    __shared__ __align__(16) float sh_h[2][4][32];   // [buf][node-in-block][channel]
    int wid = tid >> 5;          // warp id (2 warps/block)
    int j   = tid & 31;          // hidden channel
    int batch = order[bid / BPB2];
    int nbase = batch * NODES_ + (bid % BPB2) * 4;
    int n0 = nbase + wid * 2;    // nodes n0, n0+1
    int len = lengths[batch];    // uniform across warp

    ull wR[16], wZ[16], wN[16];
    #pragma unroll
    for (int p = 0; p < 16; p++) {
        wR[p] = *(const ull*)&W_hh[(j     ) * 32 + 2 * p];
        wZ[p] = *(const ull*)&W_hh[(32 + j) * 32 + 2 * p];
        wN[p] = *(const ull*)&W_hh[(64 + j) * 32 + 2 * p];
    }
    float wiR = W_ih[j], wiZ = W_ih[32 + j], wiN = W_ih[64 + j];
    float bR  = b_ih[j]      + b_hh[j];
    float bZ  = b_ih[32 + j] + b_hh[32 + j];
    float bNx = b_ih[64 + j];
    float bNh = b_hh[64 + j];

    int ra = wid * 2, rb = wid * 2 + 1;
    float h0 = 0.0f, h1 = 0.0f;
    sh_h[0][ra][j] = 0.0f;
    sh_h[0][rb][j] = 0.0f;
    __syncwarp();

    const longlong2* hrdA = (const longlong2*)sh_h[0][ra];
    const longlong2* hrdB = (const longlong2*)sh_h[0][rb];
    float* hwrA = sh_h[1][ra];
    float* hwrB = sh_h[1][rb];

    const float* xp = xT + n0;
    float2 xv = *(const float2*)xp;   // broadcast LDG.64: x for both nodes
    xp += Nn;
    for (int t = 0; t < len; t++) {
        float xt0 = xv.x, xt1 = xv.y;
        xv = *(const float2*)xp;      // row t+1 (pad row Tt on final iter)
        xp += Nn;

        ull aR0 = pack2_(fmaf(xt0, wiR, bR), 0.0f);
        ull aZ0 = pack2_(fmaf(xt0, wiZ, bZ), 0.0f);
        ull aN0 = pack2_(bNh, 0.0f);
        ull aR1 = pack2_(fmaf(xt1, wiR, bR), 0.0f);
        ull aZ1 = pack2_(fmaf(xt1, wiZ, bZ), 0.0f);
        ull aN1 = pack2_(bNh, 0.0f);
        #pragma unroll
        for (int p = 0; p < 8; p++) {
            longlong2 ha = hrdA[p];          // broadcast LDS.128: 4 h of node 0
            longlong2 hb = hrdB[p];          // broadcast LDS.128: 4 h of node 1
            ull a0 = (ull)ha.x, a1 = (ull)ha.y;
            ull b0 = (ull)hb.x, b1 = (ull)hb.y;
            aR0 = fma2_(a0, wR[2 * p], aR0);
            aR1 = fma2_(b0, wR[2 * p], aR1);
            aZ0 = fma2_(a0, wZ[2 * p], aZ0);
            aZ1 = fma2_(b0, wZ[2 * p], aZ1);
            aN0 = fma2_(a0, wN[2 * p], aN0);
            aN1 = fma2_(b0, wN[2 * p], aN1);
            aR0 = fma2_(a1, wR[2 * p + 1], aR0);
            aR1 = fma2_(b1, wR[2 * p + 1], aR1);
            aZ0 = fma2_(a1, wZ[2 * p + 1], aZ0);
            aZ1 = fma2_(b1, wZ[2 * p + 1], aZ1);
            aN0 = fma2_(a1, wN[2 * p + 1], aN0);
            aN1 = fma2_(b1, wN[2 * p + 1], aN1);
        }
        float r0 = sigm_(hsum2_(aR0));
        float r1 = sigm_(hsum2_(aR1));
        float z0 = sigm_(hsum2_(aZ0));
        float z1 = sigm_(hsum2_(aZ1));
        float nn0 = tanh_(fmaf(xt0, wiN, bNx) + r0 * hsum2_(aN0));
        float nn1 = tanh_(fmaf(xt1, wiN, bNx) + r1 * hsum2_(aN1));
        h0 = fmaf(z0, h0 - nn0, nn0);        // (1-z)*nn + z*h
        h1 = fmaf(z1, h1 - nn1, nn1);
        hwrA[j] = h0;
        hwrB[j] = h1;
        __syncwarp();
        float* tA = (float*)hrdA; hrdA = (const longlong2*)hwrA; hwrA = tA;
        float* tB = (float*)hrdB; hrdB = (const longlong2*)hwrB; hwrB = tB;
    }

    // ---- gemm0 epilogue: xw[n][o] = sum_k h[n][k] * W0[o][k], 4 own nodes ----
    sh_h[0][ra][j] = h0;
    sh_h[0][rb][j] = h1;
    __syncthreads();
    int o = tid;                 // 0..63 output channel
    float4 w[8];
    #pragma unroll
    for (int q = 0; q < 8; q++)
        w[q] = ((const float4*)W0)[o * 8 + q];
    #pragma unroll
    for (int k = 0; k < 4; k++) {
        const float4* hv = (const float4*)sh_h[0][k];
        float acc = 0.0f;
        #pragma unroll
        for (int q = 0; q < 8; q++) {
            float4 hh = hv[q];   // broadcast LDS.128
            acc = fmaf(w[q].x, hh.x, acc);
            acc = fmaf(w[q].y, hh.y, acc);
            acc = fmaf(w[q].z, hh.z, acc);
            acc = fmaf(w[q].w, hh.w, acc);
        }
        int n = nbase + k;
        xw_out[n * 64 + o]  = acc;
        xwh_out[n * 64 + o] = __float2half(acc);
    }
}

// ---------------- 4-7) aggregation (+ fused next-layer gemm) ----------------
// fp16 gather over dst-CSR + fp32 self + bias + PReLU (verified round-8 body).
// If Wnext != null: block also computes xw_{i+1} for its own 8 nodes.
__global__ void __launch_bounds__(128) agg_kernel(
    const float* __restrict__ xw, const __half* __restrict__ xwh,
    const float* __restrict__ dis2,
    const int* __restrict__ rowptr, const ull* __restrict__ edge,
    const float* __restrict__ bias,
    const float* __restrict__ prelu_a, int layer,
    const float* __restrict__ Wnext,
    float* __restrict__ xw_out, __half* __restrict__ xwh_out,
    float* __restrict__ final_out) {
    __shared__ __align__(16) float sh_res[8][64];
    int tid = threadIdx.x;           // 128 -> 8 nodes per block, 16 lanes per node
    int n = blockIdx.x * 8 + (tid >> 4);
    int l = tid & 15;
    int lane = tid & 31;
    unsigned gmask = 0xFFFFu << (lane & 16);

    const float4* __restrict__ xw4 = (const float4*)xw;
    const uint2* __restrict__ xh = (const uint2*)xwh;   // 4 halves per element
    float4 acc = xw4[n * 16 + l];
    float d2 = dis2[n];
    acc.x *= d2; acc.y *= d2; acc.z *= d2; acc.w *= d2;

    int e0 = rowptr[n], e1 = rowptr[n + 1];
    for (int e = e0; e < e1; e += 16) {
        ull rec = 0;                              // zero coef pads partial chunks
        if (e + l < e1) rec = edge[e + l];
        #pragma unroll
        for (int m = 0; m < 16; m++) {
            ull rm = __shfl_sync(gmask, rec, m, 16);
            int   sm = (int)(unsigned)rm;
            float cm = __uint_as_float((unsigned)(rm >> 32));
            uint2 hv = xh[sm * 16 + l];
            float2 f0 = __half22float2(*(__half2*)&hv.x);
            float2 f1 = __half22float2(*(__half2*)&hv.y);
            acc.x = fmaf(cm, f0.x, acc.x); acc.y = fmaf(cm, f0.y, acc.y);
            acc.z = fmaf(cm, f1.x, acc.z); acc.w = fmaf(cm, f1.y, acc.w);
        }
    }
    float4 b4 = ((const float4*)bias)[l];
    acc.x += b4.x; acc.y += b4.y; acc.z += b4.z; acc.w += b4.w;
    float a = prelu_a[layer];
    acc.x = (acc.x >= 0.f) ? acc.x : a * acc.x;
    acc.y = (acc.y >= 0.f) ? acc.y : a * acc.y;
    acc.z = (acc.z >= 0.f) ? acc.z : a * acc.z;
    acc.w = (acc.w >= 0.f) ? acc.w : a * acc.w;

    if (Wnext == nullptr) {          // final layer: write node embeddings
        ((float4*)final_out)[n * 16 + l] = acc;
        return;
    }
    ((float4*)sh_res[tid >> 4])[l] = acc;
    __syncthreads();

    // ---- fused gemm: xw_{i+1}[n][o] = sum_k res[n][k] * Wnext[o][k], 8 own nodes ----
    int o = tid & 63;
    int half = tid >> 6;             // 0 or 1
    int nbase = blockIdx.x * 8;
    #pragma unroll
    for (int k = 0; k < 4; k++) {
        int nl = k * 2 + half;
        const float4* hv = (const float4*)sh_res[nl];
        const float4* wr = (const float4*)Wnext + o * 16;
        float acc2 = 0.0f;
        #pragma unroll
        for (int q = 0; q < 16; q++) {
            float4 hh = hv[q];
            float4 ww = wr[q];
            acc2 = fmaf(ww.x, hh.x, acc2);
            acc2 = fmaf(ww.y, hh.y, acc2);
            acc2 = fmaf(ww.z, hh.z, acc2);
            acc2 = fmaf(ww.w, hh.w, acc2);
        }
        int n2 = nbase + nl;
        xw_out[n2 * 64 + o]  = acc2;
        xwh_out[n2 * 64 + o] = __float2half(acc2);
    }
}

// ---------------- 8) graph mean pooling ----------------
__global__ void graph_kernel(const float* __restrict__ node_emb, float* __restrict__ gout) {
    int b = blockIdx.x;   // 64
    int d = threadIdx.x;  // 64
    float s = 0.0f;
    #pragma unroll 8
    for (int i = 0; i < NODES_; i++)
        s += node_emb[(b * NODES_ + i) * 64 + d];
    gout[b * 64 + d] = s * (1.0f / (float)NODES_);
}

// ---------------- launch (8 kernels, single stream) ----------------
extern "C" void kernel_launch(void* const* d_in, const int* in_sizes, int n_in,
                              void* d_out, int out_size) {
    const float* x       = (const float*)d_in[0];
    const int*   ei      = (const int*)d_in[1];
    const float* ea      = (const float*)d_in[2];
    const int*   lengths = (const int*)d_in[3];
    // d_in[4] = batch (unused; batch[n] == n / NODES_)
    const float* W_ih    = (const float*)d_in[5];
    const float* W_hh    = (const float*)d_in[6];
    const float* b_ih    = (const float*)d_in[7];
    const float* b_hh    = (const float*)d_in[8];
    const float* g_w0    = (const float*)d_in[9];
    const float* g_b0    = (const float*)d_in[10];
    const float* g_ws    = (const float*)d_in[11];
    const float* g_bs    = (const float*)d_in[12];
    const float* prelu_a = (const float*)d_in[13];
    float* out = (float*)d_out;

    float *xT, *xwA, *xwB, *deg, *dis, *dis2;
    __half *xwhA, *xwhB;
    int *cnt, *rowptr, *cursor, *order;
    ull* edge;
    cudaGetSymbolAddress((void**)&xT,     d_xT);
    cudaGetSymbolAddress((void**)&xwA,    d_xwA);
    cudaGetSymbolAddress((void**)&xwhA,   d_xwhA);
    cudaGetSymbolAddress((void**)&xwB,    d_xwB);
    cudaGetSymbolAddress((void**)&xwhB,   d_xwhB);
    cudaGetSymbolAddress((void**)&deg,    d_deg);
    cudaGetSymbolAddress((void**)&dis,    d_dis);
    cudaGetSymbolAddress((void**)&dis2,   d_dis2);
    cudaGetSymbolAddress((void**)&cnt,    d_cnt);
    cudaGetSymbolAddress((void**)&rowptr, d_rowptr);
    cudaGetSymbolAddress((void**)&cursor, d_cursor);
    cudaGetSymbolAddress((void**)&order,  d_order);
    cudaGetSymbolAddress((void**)&edge,   d_edge);

    // 1: init deg/cnt/done
    init_kernel<<<8192 / 256, 256>>>(deg, cnt);
    // 2: fused transpose | edge_deg | sort  (+ last-block scan)
    fused_pre_kernel<<<NPREB, 256>>>(x, xT, ei, ea, deg, cnt, lengths, order,
                                     rowptr, cursor, dis, dis2);
    // 3: merged GRU+gemm0 | CSR fill
    gru_csr_kernel<<<NGRUB + NCSRB, 64>>>(xT, lengths, order, W_hh, W_ih, b_ih, b_hh,
                                          g_w0, xwA, xwhA, ei, ea, dis, cursor, edge);
    // 4-7: agg layers (each fuses the next layer's gemm); A/B ping-pong
    agg_kernel<<<Nn / 8, 128>>>(xwA, xwhA, dis2, rowptr, edge, g_b0, prelu_a, 0,
                                g_ws + 0 * 64 * 64, xwB, xwhB, nullptr);      // profiled
    agg_kernel<<<Nn / 8, 128>>>(xwB, xwhB, dis2, rowptr, edge, g_bs + 0 * 64, prelu_a, 1,
                                g_ws + 1 * 64 * 64, xwA, xwhA, nullptr);
    agg_kernel<<<Nn / 8, 128>>>(xwA, xwhA, dis2, rowptr, edge, g_bs + 1 * 64, prelu_a, 2,
                                g_ws + 2 * 64 * 64, xwB, xwhB, nullptr);
    agg_kernel<<<Nn / 8, 128>>>(xwB, xwhB, dis2, rowptr, edge, g_bs + 2 * 64, prelu_a, 3,
                                nullptr, nullptr, nullptr, out);
    // 8: graph embedding appended after node embeddings
    graph_kernel<<<NB, 64>>>(out, out + Nn * 64);
}